// round 5
// baseline (speedup 1.0000x reference)
#include <cuda_runtime.h>

// MyModel_83597243450144 : 4-layer LSTM autoencoder, fp32 with packed f32x2 FMA.
// B=2048, T=128, H1=128, H2=64. Gate order i,f,g,o; g uses relu, h = o*relu(c).
//
// Layout tricks (all to feed fma.rn.f32x2 / FFMA2 with zero per-iter packing):
//  - weights packed [k][u][i,f,g,o] -> one LDG.128 = two f32x2 regs (w_if, w_go)
//  - hidden state / x duplicated in shared (h,h) -> one LDS.128 = two dup f32x2
//  - accumulators pair gates: a_if = (z_i,z_f), a_go = (z_g,z_o)

#define B_ALL 2048
#define T_SEQ 128
#define BT 16
#define NBLK (B_ALL / BT)  // 128 CTAs
#define HROW 36            // shared row stride in floats (32 dup data + 4 pad), 16B-mult

typedef unsigned long long ull;

// ---- device scratch (no allocations allowed) ----
__device__ float g_U1p[128 * 512];   // [k][u*4+g]  (U1 repacked)
__device__ float g_WU2p[192 * 256];  // k<128: W2, k>=128: U2
__device__ float g_W3p[64 * 256];
__device__ float g_U3p[64 * 256];
__device__ float g_WU4p[192 * 512];  // k<64: W4, k>=64: U4
__device__ float g_h2last[B_ALL * 64];

__device__ __forceinline__ float sigmoidf_(float v) {
    return __fdividef(1.0f, 1.0f + __expf(-v));
}
__device__ __forceinline__ ull pack2_(float lo, float hi) {
    ull r;
    asm("mov.b64 %0, {%1, %2};" : "=l"(r) : "f"(lo), "f"(hi));
    return r;
}
__device__ __forceinline__ void unpack2_(ull v, float& lo, float& hi) {
    asm("mov.b64 {%0, %1}, %2;" : "=f"(lo), "=f"(hi) : "l"(v));
}
__device__ __forceinline__ ull fma2_(ull a, ull b, ull c) {
    ull d;
    asm("fma.rn.f32x2 %0, %1, %2, %3;" : "=l"(d) : "l"(a), "l"(b), "l"(c));
    return d;
}

// ---------------------------------------------------------------------------
// Weight repack: per hidden unit u, the 4 gate weights (i,f,g,o) contiguous.
// Total elements = 65536 + 49152 + 16384 + 16384 + 98304 = 245760 = 960*256.
// ---------------------------------------------------------------------------
__global__ void pack_kernel(const float* __restrict__ U1,
                            const float* __restrict__ W2, const float* __restrict__ U2,
                            const float* __restrict__ W3, const float* __restrict__ U3,
                            const float* __restrict__ W4, const float* __restrict__ U4) {
    int e = blockIdx.x * blockDim.x + threadIdx.x;
    if (e < 65536) {  // U1p: [128][512]
        int k = e >> 9, r = e & 511, u = r >> 2, g = r & 3;
        g_U1p[e] = U1[k * 512 + g * 128 + u];
        return;
    }
    int e2 = e - 65536;
    if (e2 < 49152) {  // WU2p: [192][256]
        int k = e2 >> 8, r = e2 & 255, u = r >> 2, g = r & 3;
        g_WU2p[e2] = (k < 128) ? W2[k * 256 + g * 64 + u]
                               : U2[(k - 128) * 256 + g * 64 + u];
        return;
    }
    int e3 = e2 - 49152;
    if (e3 < 16384) {  // W3p: [64][256]
        int k = e3 >> 8, r = e3 & 255, u = r >> 2, g = r & 3;
        g_W3p[e3] = W3[k * 256 + g * 64 + u];
        return;
    }
    int e4 = e3 - 16384;
    if (e4 < 16384) {  // U3p: [64][256]
        int k = e4 >> 8, r = e4 & 255, u = r >> 2, g = r & 3;
        g_U3p[e4] = U3[k * 256 + g * 64 + u];
        return;
    }
    int e5 = e4 - 16384;
    if (e5 < 98304) {  // WU4p: [192][512]
        int k = e5 >> 9, r = e5 & 511, u = r >> 2, g = r & 3;
        g_WU4p[e5] = (k < 64) ? W4[k * 512 + g * 128 + u]
                              : U4[(k - 64) * 512 + g * 128 + u];
    }
}

// ---------------------------------------------------------------------------
// Phase A: LSTM1 (H=128) + LSTM2 (H=64), 16 samples per CTA.
// hcat rows 0..127 = h1, rows 128..191 = h2; each value duplicated (h,h).
// ---------------------------------------------------------------------------
__global__ void __launch_bounds__(256, 1)
phaseA_kernel(const float* __restrict__ x, const float* __restrict__ W1,
              const float* __restrict__ b1, const float* __restrict__ b2) {
    __shared__ float hcat[192 * HROW];
    __shared__ float xs[T_SEQ * 32];  // duplicated x: [t][2b],[t][2b+1]

    const int tid = threadIdx.x;
    const int b0 = blockIdx.x * BT;

    for (int i = tid; i < T_SEQ * BT; i += 256) {
        int b = i >> 7, t = i & 127;
        float v = x[(b0 + b) * T_SEQ + t];
        xs[t * 32 + 2 * b]     = v;
        xs[t * 32 + 2 * b + 1] = v;
    }
    for (int i = tid; i < 192 * HROW; i += 256) hcat[i] = 0.0f;

    const int u1 = tid & 127, bg1 = tid >> 7;  // 8 samples each
    const int u2 = tid & 63,  bg2 = tid >> 6;  // 4 samples each

    const ulonglong2* __restrict__ U1p2  = (const ulonglong2*)g_U1p;   // [k*128+u1]
    const ulonglong2* __restrict__ WU2p2 = (const ulonglong2*)g_WU2p;  // [k*64 +u2]

    const ull w1if = pack2_(W1[u1], W1[128 + u1]);
    const ull w1go = pack2_(W1[256 + u1], W1[384 + u1]);
    const ull b1if = pack2_(b1[u1], b1[128 + u1]);
    const ull b1go = pack2_(b1[256 + u1], b1[384 + u1]);
    const ull b2if = pack2_(b2[u2], b2[64 + u2]);
    const ull b2go = pack2_(b2[128 + u2], b2[192 + u2]);

    float c1[8], c2[4];
#pragma unroll
    for (int j = 0; j < 8; j++) c1[j] = 0.0f;
#pragma unroll
    for (int j = 0; j < 4; j++) c2[j] = 0.0f;

    __syncthreads();

    for (int t = 0; t < T_SEQ; t++) {
        // ---- layer 1: z1 = x_t*W1 + h1 @ U1 + b1 ----
        ull aif[8], ago[8];
        {
            const float* xp = xs + t * 32 + bg1 * 16;
#pragma unroll
            for (int q = 0; q < 4; q++) {
                ulonglong2 xd = *(const ulonglong2*)(xp + 4 * q);
                aif[2 * q]     = fma2_(xd.x, w1if, b1if);
                ago[2 * q]     = fma2_(xd.x, w1go, b1go);
                aif[2 * q + 1] = fma2_(xd.y, w1if, b1if);
                ago[2 * q + 1] = fma2_(xd.y, w1go, b1go);
            }
        }
        const float* hp = hcat + bg1 * 16;
#pragma unroll 4
        for (int k = 0; k < 128; k++) {
            ulonglong2 w = U1p2[k * 128 + u1];
            ulonglong2 h0 = *(const ulonglong2*)(hp + k * HROW);
            ulonglong2 h1 = *(const ulonglong2*)(hp + k * HROW + 4);
            ulonglong2 h2 = *(const ulonglong2*)(hp + k * HROW + 8);
            ulonglong2 h3 = *(const ulonglong2*)(hp + k * HROW + 12);
            ull hv[8] = {h0.x, h0.y, h1.x, h1.y, h2.x, h2.y, h3.x, h3.y};
#pragma unroll
            for (int j = 0; j < 8; j++) {
                aif[j] = fma2_(hv[j], w.x, aif[j]);
                ago[j] = fma2_(hv[j], w.y, ago[j]);
            }
        }
        __syncthreads();  // all reads of old h1 complete
#pragma unroll
        for (int j = 0; j < 8; j++) {
            float zi, zf, zg, zo;
            unpack2_(aif[j], zi, zf);
            unpack2_(ago[j], zg, zo);
            float iv = sigmoidf_(zi);
            float fv = sigmoidf_(zf);
            float gv = fmaxf(zg, 0.0f);
            float ov = sigmoidf_(zo);
            float c  = fmaf(fv, c1[j], iv * gv);
            c1[j] = c;
            float h = ov * fmaxf(c, 0.0f);
            *(float2*)&hcat[u1 * HROW + bg1 * 16 + 2 * j] = make_float2(h, h);
        }
        __syncthreads();  // new h1 visible

        // ---- layer 2: z2 = h1_t @ W2 + h2 @ U2 + b2 (single K=192 loop) ----
        ull a2if[4], a2go[4];
#pragma unroll
        for (int j = 0; j < 4; j++) { a2if[j] = b2if; a2go[j] = b2go; }
        const float* hp2 = hcat + bg2 * 8;
#pragma unroll 4
        for (int k = 0; k < 192; k++) {
            ulonglong2 w = WU2p2[k * 64 + u2];
            ulonglong2 h0 = *(const ulonglong2*)(hp2 + k * HROW);
            ulonglong2 h1 = *(const ulonglong2*)(hp2 + k * HROW + 4);
            ull hv[4] = {h0.x, h0.y, h1.x, h1.y};
#pragma unroll
            for (int j = 0; j < 4; j++) {
                a2if[j] = fma2_(hv[j], w.x, a2if[j]);
                a2go[j] = fma2_(hv[j], w.y, a2go[j]);
            }
        }
        __syncthreads();  // all reads of old h2 complete
#pragma unroll
        for (int j = 0; j < 4; j++) {
            float zi, zf, zg, zo;
            unpack2_(a2if[j], zi, zf);
            unpack2_(a2go[j], zg, zo);
            float iv = sigmoidf_(zi);
            float fv = sigmoidf_(zf);
            float gv = fmaxf(zg, 0.0f);
            float ov = sigmoidf_(zo);
            float c  = fmaf(fv, c2[j], iv * gv);
            c2[j] = c;
            float h = ov * fmaxf(c, 0.0f);
            *(float2*)&hcat[(128 + u2) * HROW + bg2 * 8 + 2 * j] = make_float2(h, h);
            if (t == T_SEQ - 1) g_h2last[(b0 + bg2 * 4 + j) * 64 + u2] = h;
        }
        // next-iteration layer-1 pass only touches rows <128; the two barriers
        // above separate this write from the next read of rows >=128.
    }
}

// ---------------------------------------------------------------------------
// Phase B: RepeatVector(h2_last) -> LSTM3 (H=64) -> LSTM4 (H=128) -> Dense(1).
// hcat rows 0..63 = h3, rows 64..191 = h4 (duplicated values).
// Layer-3 input path (h2_last @ W3 + b3) is constant over t -> held in regs.
// ---------------------------------------------------------------------------
__global__ void __launch_bounds__(256, 1)
phaseB_kernel(const float* __restrict__ b3, const float* __restrict__ b4,
              const float* __restrict__ Wd, const float* __restrict__ bd,
              float* __restrict__ out) {
    __shared__ float hcat[192 * HROW];
    __shared__ float h2T[64 * 32];  // duplicated: [k][2b],[k][2b+1]

    const int tid = threadIdx.x;
    const int b0 = blockIdx.x * BT;

    for (int i = tid; i < 64 * BT; i += 256) {
        int b = i >> 6, k = i & 63;
        float v = g_h2last[(b0 + b) * 64 + k];
        h2T[k * 32 + 2 * b]     = v;
        h2T[k * 32 + 2 * b + 1] = v;
    }
    for (int i = tid; i < 192 * HROW; i += 256) hcat[i] = 0.0f;

    const int u3 = tid & 63,  bg  = tid >> 6;  // 4 samples
    const int u4 = tid & 127, bg2 = tid >> 7;  // 8 samples
    const int lane16 = tid & 15, bq = tid >> 4;

    const ulonglong2* __restrict__ W3p2  = (const ulonglong2*)g_W3p;
    const ulonglong2* __restrict__ U3p2  = (const ulonglong2*)g_U3p;
    const ulonglong2* __restrict__ WU4p2 = (const ulonglong2*)g_WU4p;

    const ull b4if = pack2_(b4[u4], b4[128 + u4]);
    const ull b4go = pack2_(b4[256 + u4], b4[384 + u4]);
    float wd[8];
#pragma unroll
    for (int r = 0; r < 8; r++) wd[r] = Wd[lane16 + 16 * r];
    const float bdv = bd[0];

    __syncthreads();

    // precompute zx3 = h2_last @ W3 + b3 (constant over t) into registers
    ull zif[4], zgo[4];
    {
        const ull b3if = pack2_(b3[u3], b3[64 + u3]);
        const ull b3go = pack2_(b3[128 + u3], b3[192 + u3]);
#pragma unroll
        for (int j = 0; j < 4; j++) { zif[j] = b3if; zgo[j] = b3go; }
        const float* hpx = h2T + bg * 8;
#pragma unroll 4
        for (int k = 0; k < 64; k++) {
            ulonglong2 w = W3p2[k * 64 + u3];
            ulonglong2 h0 = *(const ulonglong2*)(hpx + k * 32);
            ulonglong2 h1 = *(const ulonglong2*)(hpx + k * 32 + 4);
            ull hv[4] = {h0.x, h0.y, h1.x, h1.y};
#pragma unroll
            for (int j = 0; j < 4; j++) {
                zif[j] = fma2_(hv[j], w.x, zif[j]);
                zgo[j] = fma2_(hv[j], w.y, zgo[j]);
            }
        }
    }

    float c3[4], c4[8];
#pragma unroll
    for (int j = 0; j < 4; j++) c3[j] = 0.0f;
#pragma unroll
    for (int j = 0; j < 8; j++) c4[j] = 0.0f;

    for (int t = 0; t < T_SEQ; t++) {
        // ---- layer 3: z3 = zx3 + h3 @ U3 ----
        ull a3if[4], a3go[4];
#pragma unroll
        for (int j = 0; j < 4; j++) { a3if[j] = zif[j]; a3go[j] = zgo[j]; }
        const float* hp3 = hcat + bg * 8;
#pragma unroll 4
        for (int k = 0; k < 64; k++) {
            ulonglong2 w = U3p2[k * 64 + u3];
            ulonglong2 h0 = *(const ulonglong2*)(hp3 + k * HROW);
            ulonglong2 h1 = *(const ulonglong2*)(hp3 + k * HROW + 4);
            ull hv[4] = {h0.x, h0.y, h1.x, h1.y};
#pragma unroll
            for (int j = 0; j < 4; j++) {
                a3if[j] = fma2_(hv[j], w.x, a3if[j]);
                a3go[j] = fma2_(hv[j], w.y, a3go[j]);
            }
        }
        __syncthreads();
#pragma unroll
        for (int j = 0; j < 4; j++) {
            float zi, zf, zg, zo;
            unpack2_(a3if[j], zi, zf);
            unpack2_(a3go[j], zg, zo);
            float iv = sigmoidf_(zi);
            float fv = sigmoidf_(zf);
            float gv = fmaxf(zg, 0.0f);
            float ov = sigmoidf_(zo);
            float c  = fmaf(fv, c3[j], iv * gv);
            c3[j] = c;
            float h = ov * fmaxf(c, 0.0f);
            *(float2*)&hcat[u3 * HROW + bg * 8 + 2 * j] = make_float2(h, h);
        }
        __syncthreads();

        // ---- layer 4: z4 = h3_t @ W4 + h4 @ U4 + b4 (K=192) ----
        ull a4if[8], a4go[8];
#pragma unroll
        for (int j = 0; j < 8; j++) { a4if[j] = b4if; a4go[j] = b4go; }
        const float* hp4 = hcat + bg2 * 16;
#pragma unroll 4
        for (int k = 0; k < 192; k++) {
            ulonglong2 w = WU4p2[k * 128 + u4];
            ulonglong2 h0 = *(const ulonglong2*)(hp4 + k * HROW);
            ulonglong2 h1 = *(const ulonglong2*)(hp4 + k * HROW + 4);
            ulonglong2 h2 = *(const ulonglong2*)(hp4 + k * HROW + 8);
            ulonglong2 h3 = *(const ulonglong2*)(hp4 + k * HROW + 12);
            ull hv[8] = {h0.x, h0.y, h1.x, h1.y, h2.x, h2.y, h3.x, h3.y};
#pragma unroll
            for (int j = 0; j < 8; j++) {
                a4if[j] = fma2_(hv[j], w.x, a4if[j]);
                a4go[j] = fma2_(hv[j], w.y, a4go[j]);
            }
        }
        __syncthreads();
#pragma unroll
        for (int j = 0; j < 8; j++) {
            float zi, zf, zg, zo;
            unpack2_(a4if[j], zi, zf);
            unpack2_(a4go[j], zg, zo);
            float iv = sigmoidf_(zi);
            float fv = sigmoidf_(zf);
            float gv = fmaxf(zg, 0.0f);
            float ov = sigmoidf_(zo);
            float c  = fmaf(fv, c4[j], iv * gv);
            c4[j] = c;
            float h = ov * fmaxf(c, 0.0f);
            *(float2*)&hcat[(64 + u4) * HROW + bg2 * 16 + 2 * j] = make_float2(h, h);
        }
        __syncthreads();

        // ---- dense: out[b][t] = h4 . Wd + bd (16-lane tree per sample) ----
        float s = 0.0f;
#pragma unroll
        for (int r = 0; r < 8; r++)
            s = fmaf(hcat[(64 + lane16 + 16 * r) * HROW + bq * 2], wd[r], s);
        s += __shfl_xor_sync(0xffffffffu, s, 8);
        s += __shfl_xor_sync(0xffffffffu, s, 4);
        s += __shfl_xor_sync(0xffffffffu, s, 2);
        s += __shfl_xor_sync(0xffffffffu, s, 1);
        if (lane16 == 0) out[(b0 + bq) * T_SEQ + t] = s + bdv;
        // dense reads complete before the first barrier of the next iteration;
        // h4 rows are rewritten only after two more barriers.
    }
}

// ---------------------------------------------------------------------------
extern "C" void kernel_launch(void* const* d_in, const int* in_sizes, int n_in,
                              void* d_out, int out_size) {
    const float* x  = (const float*)d_in[0];
    const float* W1 = (const float*)d_in[1];
    const float* U1 = (const float*)d_in[2];
    const float* b1 = (const float*)d_in[3];
    const float* W2 = (const float*)d_in[4];
    const float* U2 = (const float*)d_in[5];
    const float* b2 = (const float*)d_in[6];
    const float* W3 = (const float*)d_in[7];
    const float* U3 = (const float*)d_in[8];
    const float* b3 = (const float*)d_in[9];
    const float* W4 = (const float*)d_in[10];
    const float* U4 = (const float*)d_in[11];
    const float* b4 = (const float*)d_in[12];
    const float* Wd = (const float*)d_in[13];
    const float* bd = (const float*)d_in[14];
    float* out = (float*)d_out;

    pack_kernel<<<960, 256>>>(U1, W2, U2, W3, U3, W4, U4);
    phaseA_kernel<<<NBLK, 256>>>(x, W1, b1, b2);
    phaseB_kernel<<<NBLK, 256>>>(b3, b4, Wd, bd, out);
}

// round 6
// speedup vs baseline: 1.0020x; 1.0020x over previous
#include <cuda_runtime.h>

// MyModel_83597243450144 : 4-layer LSTM autoencoder, fp32 with packed f32x2 FMA.
// B=2048, T=128, H1=128, H2=64. Gate order i,f,g,o; g uses relu, h = o*relu(c).
//
// Layout tricks (all to feed fma.rn.f32x2 / FFMA2 with zero per-iter packing):
//  - weights packed [k][u][i,f,g,o] -> one LDG.128 = two f32x2 regs (w_if, w_go)
//  - hidden state / x duplicated in shared (h,h) -> one LDS.128 = two dup f32x2
//  - accumulators pair gates: a_if = (z_i,z_f), a_go = (z_g,z_o)

#define B_ALL 2048
#define T_SEQ 128
#define BT 16
#define NBLK (B_ALL / BT)  // 128 CTAs
#define HROW 36            // shared row stride in floats (32 dup data + 4 pad), 16B-mult

typedef unsigned long long ull;

// ---- device scratch (no allocations allowed) ----
__device__ float g_U1p[128 * 512];   // [k][u*4+g]  (U1 repacked)
__device__ float g_WU2p[192 * 256];  // k<128: W2, k>=128: U2
__device__ float g_W3p[64 * 256];
__device__ float g_U3p[64 * 256];
__device__ float g_WU4p[192 * 512];  // k<64: W4, k>=64: U4
__device__ float g_h2last[B_ALL * 64];

__device__ __forceinline__ float sigmoidf_(float v) {
    return __fdividef(1.0f, 1.0f + __expf(-v));
}
__device__ __forceinline__ ull pack2_(float lo, float hi) {
    ull r;
    asm("mov.b64 %0, {%1, %2};" : "=l"(r) : "f"(lo), "f"(hi));
    return r;
}
__device__ __forceinline__ void unpack2_(ull v, float& lo, float& hi) {
    asm("mov.b64 {%0, %1}, %2;" : "=f"(lo), "=f"(hi) : "l"(v));
}
__device__ __forceinline__ ull fma2_(ull a, ull b, ull c) {
    ull d;
    asm("fma.rn.f32x2 %0, %1, %2, %3;" : "=l"(d) : "l"(a), "l"(b), "l"(c));
    return d;
}

// ---------------------------------------------------------------------------
// Weight repack: per hidden unit u, the 4 gate weights (i,f,g,o) contiguous.
// Total elements = 65536 + 49152 + 16384 + 16384 + 98304 = 245760 = 960*256.
// ---------------------------------------------------------------------------
__global__ void pack_kernel(const float* __restrict__ U1,
                            const float* __restrict__ W2, const float* __restrict__ U2,
                            const float* __restrict__ W3, const float* __restrict__ U3,
                            const float* __restrict__ W4, const float* __restrict__ U4) {
    int e = blockIdx.x * blockDim.x + threadIdx.x;
    if (e < 65536) {  // U1p: [128][512]
        int k = e >> 9, r = e & 511, u = r >> 2, g = r & 3;
        g_U1p[e] = U1[k * 512 + g * 128 + u];
        return;
    }
    int e2 = e - 65536;
    if (e2 < 49152) {  // WU2p: [192][256]
        int k = e2 >> 8, r = e2 & 255, u = r >> 2, g = r & 3;
        g_WU2p[e2] = (k < 128) ? W2[k * 256 + g * 64 + u]
                               : U2[(k - 128) * 256 + g * 64 + u];
        return;
    }
    int e3 = e2 - 49152;
    if (e3 < 16384) {  // W3p: [64][256]
        int k = e3 >> 8, r = e3 & 255, u = r >> 2, g = r & 3;
        g_W3p[e3] = W3[k * 256 + g * 64 + u];
        return;
    }
    int e4 = e3 - 16384;
    if (e4 < 16384) {  // U3p: [64][256]
        int k = e4 >> 8, r = e4 & 255, u = r >> 2, g = r & 3;
        g_U3p[e4] = U3[k * 256 + g * 64 + u];
        return;
    }
    int e5 = e4 - 16384;
    if (e5 < 98304) {  // WU4p: [192][512]
        int k = e5 >> 9, r = e5 & 511, u = r >> 2, g = r & 3;
        g_WU4p[e5] = (k < 64) ? W4[k * 512 + g * 128 + u]
                              : U4[(k - 64) * 512 + g * 128 + u];
    }
}

// ---------------------------------------------------------------------------
// Phase A: LSTM1 (H=128) + LSTM2 (H=64), 16 samples per CTA.
// hcat rows 0..127 = h1, rows 128..191 = h2; each value duplicated (h,h).
// ---------------------------------------------------------------------------
__global__ void __launch_bounds__(256, 1)
phaseA_kernel(const float* __restrict__ x, const float* __restrict__ W1,
              const float* __restrict__ b1, const float* __restrict__ b2) {
    __shared__ float hcat[192 * HROW];
    __shared__ float xs[T_SEQ * 32];  // duplicated x: [t][2b],[t][2b+1]

    const int tid = threadIdx.x;
    const int b0 = blockIdx.x * BT;

    for (int i = tid; i < T_SEQ * BT; i += 256) {
        int b = i >> 7, t = i & 127;
        float v = x[(b0 + b) * T_SEQ + t];
        xs[t * 32 + 2 * b]     = v;
        xs[t * 32 + 2 * b + 1] = v;
    }
    for (int i = tid; i < 192 * HROW; i += 256) hcat[i] = 0.0f;

    const int u1 = tid & 127, bg1 = tid >> 7;  // 8 samples each
    const int u2 = tid & 63,  bg2 = tid >> 6;  // 4 samples each

    const ulonglong2* __restrict__ U1p2  = (const ulonglong2*)g_U1p;   // [k*128+u1]
    const ulonglong2* __restrict__ WU2p2 = (const ulonglong2*)g_WU2p;  // [k*64 +u2]

    const ull w1if = pack2_(W1[u1], W1[128 + u1]);
    const ull w1go = pack2_(W1[256 + u1], W1[384 + u1]);
    const ull b1if = pack2_(b1[u1], b1[128 + u1]);
    const ull b1go = pack2_(b1[256 + u1], b1[384 + u1]);
    const ull b2if = pack2_(b2[u2], b2[64 + u2]);
    const ull b2go = pack2_(b2[128 + u2], b2[192 + u2]);

    float c1[8], c2[4];
#pragma unroll
    for (int j = 0; j < 8; j++) c1[j] = 0.0f;
#pragma unroll
    for (int j = 0; j < 4; j++) c2[j] = 0.0f;

    __syncthreads();

    for (int t = 0; t < T_SEQ; t++) {
        // ---- layer 1: z1 = x_t*W1 + h1 @ U1 + b1 ----
        ull aif[8], ago[8];
        {
            const float* xp = xs + t * 32 + bg1 * 16;
#pragma unroll
            for (int q = 0; q < 4; q++) {
                ulonglong2 xd = *(const ulonglong2*)(xp + 4 * q);
                aif[2 * q]     = fma2_(xd.x, w1if, b1if);
                ago[2 * q]     = fma2_(xd.x, w1go, b1go);
                aif[2 * q + 1] = fma2_(xd.y, w1if, b1if);
                ago[2 * q + 1] = fma2_(xd.y, w1go, b1go);
            }
        }
        const float* hp = hcat + bg1 * 16;
#pragma unroll 4
        for (int k = 0; k < 128; k++) {
            ulonglong2 w = U1p2[k * 128 + u1];
            ulonglong2 h0 = *(const ulonglong2*)(hp + k * HROW);
            ulonglong2 h1 = *(const ulonglong2*)(hp + k * HROW + 4);
            ulonglong2 h2 = *(const ulonglong2*)(hp + k * HROW + 8);
            ulonglong2 h3 = *(const ulonglong2*)(hp + k * HROW + 12);
            ull hv[8] = {h0.x, h0.y, h1.x, h1.y, h2.x, h2.y, h3.x, h3.y};
#pragma unroll
            for (int j = 0; j < 8; j++) {
                aif[j] = fma2_(hv[j], w.x, aif[j]);
                ago[j] = fma2_(hv[j], w.y, ago[j]);
            }
        }
        __syncthreads();  // all reads of old h1 complete
#pragma unroll
        for (int j = 0; j < 8; j++) {
            float zi, zf, zg, zo;
            unpack2_(aif[j], zi, zf);
            unpack2_(ago[j], zg, zo);
            float iv = sigmoidf_(zi);
            float fv = sigmoidf_(zf);
            float gv = fmaxf(zg, 0.0f);
            float ov = sigmoidf_(zo);
            float c  = fmaf(fv, c1[j], iv * gv);
            c1[j] = c;
            float h = ov * fmaxf(c, 0.0f);
            *(float2*)&hcat[u1 * HROW + bg1 * 16 + 2 * j] = make_float2(h, h);
        }
        __syncthreads();  // new h1 visible

        // ---- layer 2: z2 = h1_t @ W2 + h2 @ U2 + b2 (single K=192 loop) ----
        ull a2if[4], a2go[4];
#pragma unroll
        for (int j = 0; j < 4; j++) { a2if[j] = b2if; a2go[j] = b2go; }
        const float* hp2 = hcat + bg2 * 8;
#pragma unroll 4
        for (int k = 0; k < 192; k++) {
            ulonglong2 w = WU2p2[k * 64 + u2];
            ulonglong2 h0 = *(const ulonglong2*)(hp2 + k * HROW);
            ulonglong2 h1 = *(const ulonglong2*)(hp2 + k * HROW + 4);
            ull hv[4] = {h0.x, h0.y, h1.x, h1.y};
#pragma unroll
            for (int j = 0; j < 4; j++) {
                a2if[j] = fma2_(hv[j], w.x, a2if[j]);
                a2go[j] = fma2_(hv[j], w.y, a2go[j]);
            }
        }
        __syncthreads();  // all reads of old h2 complete
#pragma unroll
        for (int j = 0; j < 4; j++) {
            float zi, zf, zg, zo;
            unpack2_(a2if[j], zi, zf);
            unpack2_(a2go[j], zg, zo);
            float iv = sigmoidf_(zi);
            float fv = sigmoidf_(zf);
            float gv = fmaxf(zg, 0.0f);
            float ov = sigmoidf_(zo);
            float c  = fmaf(fv, c2[j], iv * gv);
            c2[j] = c;
            float h = ov * fmaxf(c, 0.0f);
            *(float2*)&hcat[(128 + u2) * HROW + bg2 * 8 + 2 * j] = make_float2(h, h);
            if (t == T_SEQ - 1) g_h2last[(b0 + bg2 * 4 + j) * 64 + u2] = h;
        }
        // next-iteration layer-1 pass only touches rows <128; the two barriers
        // above separate this write from the next read of rows >=128.
    }
}

// ---------------------------------------------------------------------------
// Phase B: RepeatVector(h2_last) -> LSTM3 (H=64) -> LSTM4 (H=128) -> Dense(1).
// hcat rows 0..63 = h3, rows 64..191 = h4 (duplicated values).
// Layer-3 input path (h2_last @ W3 + b3) is constant over t -> held in regs.
// ---------------------------------------------------------------------------
__global__ void __launch_bounds__(256, 1)
phaseB_kernel(const float* __restrict__ b3, const float* __restrict__ b4,
              const float* __restrict__ Wd, const float* __restrict__ bd,
              float* __restrict__ out) {
    __shared__ float hcat[192 * HROW];
    __shared__ float h2T[64 * 32];  // duplicated: [k][2b],[k][2b+1]

    const int tid = threadIdx.x;
    const int b0 = blockIdx.x * BT;

    for (int i = tid; i < 64 * BT; i += 256) {
        int b = i >> 6, k = i & 63;
        float v = g_h2last[(b0 + b) * 64 + k];
        h2T[k * 32 + 2 * b]     = v;
        h2T[k * 32 + 2 * b + 1] = v;
    }
    for (int i = tid; i < 192 * HROW; i += 256) hcat[i] = 0.0f;

    const int u3 = tid & 63,  bg  = tid >> 6;  // 4 samples
    const int u4 = tid & 127, bg2 = tid >> 7;  // 8 samples
    const int lane16 = tid & 15, bq = tid >> 4;

    const ulonglong2* __restrict__ W3p2  = (const ulonglong2*)g_W3p;
    const ulonglong2* __restrict__ U3p2  = (const ulonglong2*)g_U3p;
    const ulonglong2* __restrict__ WU4p2 = (const ulonglong2*)g_WU4p;

    const ull b4if = pack2_(b4[u4], b4[128 + u4]);
    const ull b4go = pack2_(b4[256 + u4], b4[384 + u4]);
    float wd[8];
#pragma unroll
    for (int r = 0; r < 8; r++) wd[r] = Wd[lane16 + 16 * r];
    const float bdv = bd[0];

    __syncthreads();

    // precompute zx3 = h2_last @ W3 + b3 (constant over t) into registers
    ull zif[4], zgo[4];
    {
        const ull b3if = pack2_(b3[u3], b3[64 + u3]);
        const ull b3go = pack2_(b3[128 + u3], b3[192 + u3]);
#pragma unroll
        for (int j = 0; j < 4; j++) { zif[j] = b3if; zgo[j] = b3go; }
        const float* hpx = h2T + bg * 8;
#pragma unroll 4
        for (int k = 0; k < 64; k++) {
            ulonglong2 w = W3p2[k * 64 + u3];
            ulonglong2 h0 = *(const ulonglong2*)(hpx + k * 32);
            ulonglong2 h1 = *(const ulonglong2*)(hpx + k * 32 + 4);
            ull hv[4] = {h0.x, h0.y, h1.x, h1.y};
#pragma unroll
            for (int j = 0; j < 4; j++) {
                zif[j] = fma2_(hv[j], w.x, zif[j]);
                zgo[j] = fma2_(hv[j], w.y, zgo[j]);
            }
        }
    }

    float c3[4], c4[8];
#pragma unroll
    for (int j = 0; j < 4; j++) c3[j] = 0.0f;
#pragma unroll
    for (int j = 0; j < 8; j++) c4[j] = 0.0f;

    for (int t = 0; t < T_SEQ; t++) {
        // ---- layer 3: z3 = zx3 + h3 @ U3 ----
        ull a3if[4], a3go[4];
#pragma unroll
        for (int j = 0; j < 4; j++) { a3if[j] = zif[j]; a3go[j] = zgo[j]; }
        const float* hp3 = hcat + bg * 8;
#pragma unroll 4
        for (int k = 0; k < 64; k++) {
            ulonglong2 w = U3p2[k * 64 + u3];
            ulonglong2 h0 = *(const ulonglong2*)(hp3 + k * HROW);
            ulonglong2 h1 = *(const ulonglong2*)(hp3 + k * HROW + 4);
            ull hv[4] = {h0.x, h0.y, h1.x, h1.y};
#pragma unroll
            for (int j = 0; j < 4; j++) {
                a3if[j] = fma2_(hv[j], w.x, a3if[j]);
                a3go[j] = fma2_(hv[j], w.y, a3go[j]);
            }
        }
        __syncthreads();
#pragma unroll
        for (int j = 0; j < 4; j++) {
            float zi, zf, zg, zo;
            unpack2_(a3if[j], zi, zf);
            unpack2_(a3go[j], zg, zo);
            float iv = sigmoidf_(zi);
            float fv = sigmoidf_(zf);
            float gv = fmaxf(zg, 0.0f);
            float ov = sigmoidf_(zo);
            float c  = fmaf(fv, c3[j], iv * gv);
            c3[j] = c;
            float h = ov * fmaxf(c, 0.0f);
            *(float2*)&hcat[u3 * HROW + bg * 8 + 2 * j] = make_float2(h, h);
        }
        __syncthreads();

        // ---- layer 4: z4 = h3_t @ W4 + h4 @ U4 + b4 (K=192) ----
        ull a4if[8], a4go[8];
#pragma unroll
        for (int j = 0; j < 8; j++) { a4if[j] = b4if; a4go[j] = b4go; }
        const float* hp4 = hcat + bg2 * 16;
#pragma unroll 4
        for (int k = 0; k < 192; k++) {
            ulonglong2 w = WU4p2[k * 128 + u4];
            ulonglong2 h0 = *(const ulonglong2*)(hp4 + k * HROW);
            ulonglong2 h1 = *(const ulonglong2*)(hp4 + k * HROW + 4);
            ulonglong2 h2 = *(const ulonglong2*)(hp4 + k * HROW + 8);
            ulonglong2 h3 = *(const ulonglong2*)(hp4 + k * HROW + 12);
            ull hv[8] = {h0.x, h0.y, h1.x, h1.y, h2.x, h2.y, h3.x, h3.y};
#pragma unroll
            for (int j = 0; j < 8; j++) {
                a4if[j] = fma2_(hv[j], w.x, a4if[j]);
                a4go[j] = fma2_(hv[j], w.y, a4go[j]);
            }
        }
        __syncthreads();
#pragma unroll
        for (int j = 0; j < 8; j++) {
            float zi, zf, zg, zo;
            unpack2_(a4if[j], zi, zf);
            unpack2_(a4go[j], zg, zo);
            float iv = sigmoidf_(zi);
            float fv = sigmoidf_(zf);
            float gv = fmaxf(zg, 0.0f);
            float ov = sigmoidf_(zo);
            float c  = fmaf(fv, c4[j], iv * gv);
            c4[j] = c;
            float h = ov * fmaxf(c, 0.0f);
            *(float2*)&hcat[(64 + u4) * HROW + bg2 * 16 + 2 * j] = make_float2(h, h);
        }
        __syncthreads();

        // ---- dense: out[b][t] = h4 . Wd + bd (16-lane tree per sample) ----
        float s = 0.0f;
#pragma unroll
        for (int r = 0; r < 8; r++)
            s = fmaf(hcat[(64 + lane16 + 16 * r) * HROW + bq * 2], wd[r], s);
        s += __shfl_xor_sync(0xffffffffu, s, 8);
        s += __shfl_xor_sync(0xffffffffu, s, 4);
        s += __shfl_xor_sync(0xffffffffu, s, 2);
        s += __shfl_xor_sync(0xffffffffu, s, 1);
        if (lane16 == 0) out[(b0 + bq) * T_SEQ + t] = s + bdv;
        // dense reads complete before the first barrier of the next iteration;
        // h4 rows are rewritten only after two more barriers.
    }
}

// ---------------------------------------------------------------------------
extern "C" void kernel_launch(void* const* d_in, const int* in_sizes, int n_in,
                              void* d_out, int out_size) {
    const float* x  = (const float*)d_in[0];
    const float* W1 = (const float*)d_in[1];
    const float* U1 = (const float*)d_in[2];
    const float* b1 = (const float*)d_in[3];
    const float* W2 = (const float*)d_in[4];
    const float* U2 = (const float*)d_in[5];
    const float* b2 = (const float*)d_in[6];
    const float* W3 = (const float*)d_in[7];
    const float* U3 = (const float*)d_in[8];
    const float* b3 = (const float*)d_in[9];
    const float* W4 = (const float*)d_in[10];
    const float* U4 = (const float*)d_in[11];
    const float* b4 = (const float*)d_in[12];
    const float* Wd = (const float*)d_in[13];
    const float* bd = (const float*)d_in[14];
    float* out = (float*)d_out;

    pack_kernel<<<960, 256>>>(U1, W2, U2, W3, U3, W4, U4);
    phaseA_kernel<<<NBLK, 256>>>(x, W1, b1, b2);
    phaseB_kernel<<<NBLK, 256>>>(b3, b4, Wd, bd, out);
}